// round 14
// baseline (speedup 1.0000x reference)
#include <cuda_runtime.h>
#include <cuda_bf16.h>
#include <math.h>

#define HD   20
#define TPB  128
#define CH_W 12
#define XB   144
#define KW   4          // steps per barrier window
#define RING 8          // 2*KW ring slots

typedef unsigned long long ull;

__device__ __forceinline__ float tanh_fast(float x) {
    float y; asm("tanh.approx.f32 %0, %1;" : "=f"(y) : "f"(x)); return y;
}
__device__ __forceinline__ ull pack2(float a, float b) {
    ull r; asm("mov.b64 %0, {%1,%2};" : "=l"(r) : "f"(a), "f"(b)); return r;
}
__device__ __forceinline__ float2 unpack2(ull p) {
    float2 v; asm("mov.b64 {%0,%1}, %2;" : "=f"(v.x), "=f"(v.y) : "l"(p)); return v;
}
__device__ __forceinline__ ull ffma2(ull a, ull b, ull c) {
    ull r; asm("fma.rn.f32x2 %0, %1, %2, %3;" : "=l"(r) : "l"(a), "l"(b), "l"(c)); return r;
}
__device__ __forceinline__ float hsum(ull p) {
    float2 v = unpack2(p); return v.x + v.y;
}

__device__ __forceinline__ void lstm_act4(ull aI, ull aF, ull aG, ull aO,
                                          float& cst, float& h) {
    float pi = hsum(aI), pf = hsum(aF), pg = hsum(aG), po = hsum(aO);
    float gi = fmaf(tanh_fast(0.5f * pi), 0.5f, 0.5f);
    float gf = fmaf(tanh_fast(0.5f * pf), 0.5f, 0.5f);
    float gg = tanh_fast(pg);
    float go = fmaf(tanh_fast(0.5f * po), 0.5f, 0.5f);
    cst = fmaf(gf, cst, gi * gg);
    h   = go * tanh_fast(cst);
}

// 20-dim dot for 4 gates; HB = float4-pair view of 20 floats (+12 zero pad).
#define DOT20(HB, aI, aF, aG, aO) do {                                        \
    _Pragma("unroll")                                                         \
    for (int j = 0; j < 5; j++) {                                             \
        ulonglong2 hp = (HB)[j];                                              \
        aI = ffma2(wI[2*j], hp.x, aI); aI = ffma2(wI[2*j+1], hp.y, aI);       \
        aF = ffma2(wF[2*j], hp.x, aF); aF = ffma2(wF[2*j+1], hp.y, aF);       \
        aG = ffma2(wG[2*j], hp.x, aG); aG = ffma2(wG[2*j+1], hp.y, aG);       \
        aO = ffma2(wO[2*j], hp.x, aO); aO = ffma2(wO[2*j+1], hp.y, aO);       \
    }                                                                         \
} while (0)

// Stage bodies (T = absolute step index within [0, span))
#define L1BODY(T) do {                                                        \
    float2 xv = xbuf[T];                                                      \
    ull xp = pack2(xv.x, xv.y);                                               \
    ull aI = ffma2(wxI, xp, bI);                                              \
    ull aF = ffma2(wxF, xp, bF);                                              \
    ull aG = ffma2(wxG, xp, bG);                                              \
    ull aO = ffma2(wxO, xp, bO);                                              \
    const ulonglong2* hb =                                                    \
        (const ulonglong2*)h0ring[((T) + RING - 1) & (RING - 1)];             \
    DOT20(hb, aI, aF, aG, aO);                                                \
    lstm_act4(aI, aF, aG, aO, cst, h);                                        \
    h0ring[(T) & (RING - 1)][u] = h;                                          \
} while (0)

#define PROJBODY(T) do {                                                      \
    ull aI = bI, aF = bF, aG = bG, aO = bO;                                   \
    const ulonglong2* yb = (const ulonglong2*)h0ring[(T) & (RING - 1)];       \
    DOT20(yb, aI, aF, aG, aO);                                                \
    prring[(T) & (RING - 1)][u] =                                             \
        make_float4(hsum(aI), hsum(aF), hsum(aG), hsum(aO));                  \
} while (0)

#define L2BODY(T) do {                                                        \
    float4 pv = prring[(T) & (RING - 1)][u];                                  \
    ull aI = pack2(pv.x, 0.f), aF = pack2(pv.y, 0.f);                         \
    ull aG = pack2(pv.z, 0.f), aO = pack2(pv.w, 0.f);                         \
    const ulonglong2* hb =                                                    \
        (const ulonglong2*)h1ring[((T) + RING - 1) & (RING - 1)];             \
    DOT20(hb, aI, aF, aG, aO);                                                \
    lstm_act4(aI, aF, aG, aO, cst, h);                                        \
    h1ring[(T) & (RING - 1)][u] = h;                                          \
} while (0)

#define HEADBODY(T) do {                                                      \
    float hv = h1ring[(T) & (RING - 1)][u];                                   \
    float part = hv * wlin_u;                                                 \
    part += __shfl_xor_sync(0xFFFFFFFFu, part, 16);                           \
    part += __shfl_xor_sync(0xFFFFFFFFu, part, 8);                            \
    part += __shfl_xor_sync(0xFFFFFFFFu, part, 4);                            \
    part += __shfl_xor_sync(0xFFFFFFFFu, part, 2);                            \
    part += __shfl_xor_sync(0xFFFFFFFFu, part, 1);                            \
    if (lane == 0) out[s1 + (T)] = fmaf(part, 0.01f, blinsc);                 \
} while (0)

// 128 threads/block, ONE chunk per block, 4-warp window pipeline (KW=4).
// STAGE ROTATION: stage = (wid + bid/148) & 3, so the four co-resident
// blocks on an SM (bid, bid+148, bid+296, bid+444 — classic LUT placement)
// put DIFFERENT stages on each SMSP. Without this, all L2 warps pile onto
// SMSP1 (wid%4) and its 1 instr/cy issue port paces the whole kernel.
//   stage 0: L1 LSTM  window w    -> h0ring[t&7]
//   stage 2: proj     window w-1  -> prring[tp&7]
//   stage 1: L2 LSTM  window w-2  -> h1ring[t1&7]
//   stage 3: linear head + store, window w-3
__global__ __launch_bounds__(TPB, 4)
void lstm_opt_kernel(const float* __restrict__ grad,
                     const float* __restrict__ Wih0, const float* __restrict__ Whh0,
                     const float* __restrict__ bih0, const float* __restrict__ bhh0,
                     const float* __restrict__ Wih1, const float* __restrict__ Whh1,
                     const float* __restrict__ bih1, const float* __restrict__ bhh1,
                     const float* __restrict__ Wlin, const float* __restrict__ blin,
                     float* __restrict__ out, int N, int out_size, int chl)
{
    __shared__ __align__(16) float2 xbuf[XB];
    __shared__ __align__(16) float  h0ring[RING][32];
    __shared__ __align__(16) float4 prring[RING][32];
    __shared__ __align__(16) float  h1ring[RING][32];

    const int tid  = threadIdx.x;
    const int wid  = tid >> 5;
    const int lane = tid & 31;
    const int u    = lane;
    const bool act = (u < HD);
    // rotate stages across co-resident blocks to balance SMSP issue load
    const int stage = (wid + (int)(blockIdx.x / 148)) & 3;

    // ---- per-warp weights: per-gate, k-pair packed ----
    ull wI[10], wF[10], wG[10], wO[10];
    ull bI = 0ull, bF = 0ull, bG = 0ull, bO = 0ull;
    ull wxI = 0ull, wxF = 0ull, wxG = 0ull, wxO = 0ull;
    float wlin_u = 0.f;
    #pragma unroll
    for (int k = 0; k < 10; k++) { wI[k]=0ull; wF[k]=0ull; wG[k]=0ull; wO[k]=0ull; }

    if (act) {
        if (stage < 3) {
            const float* W = (stage == 0) ? Whh0 : (stage == 1) ? Whh1 : Wih1;
            #pragma unroll
            for (int k = 0; k < 10; k++) {
                wI[k] = pack2(W[u * HD + 2*k],            W[u * HD + 2*k + 1]);
                wF[k] = pack2(W[(HD + u) * HD + 2*k],     W[(HD + u) * HD + 2*k + 1]);
                wG[k] = pack2(W[(2 * HD + u) * HD + 2*k], W[(2 * HD + u) * HD + 2*k + 1]);
                wO[k] = pack2(W[(3 * HD + u) * HD + 2*k], W[(3 * HD + u) * HD + 2*k + 1]);
            }
        }
        if (stage == 0) {         // L1: x-projection weights + L1 biases
            wxI = pack2(Wih0[u * 2 + 0],            Wih0[u * 2 + 1]);
            wxF = pack2(Wih0[(HD + u) * 2 + 0],     Wih0[(HD + u) * 2 + 1]);
            wxG = pack2(Wih0[(2 * HD + u) * 2 + 0], Wih0[(2 * HD + u) * 2 + 1]);
            wxO = pack2(Wih0[(3 * HD + u) * 2 + 0], Wih0[(3 * HD + u) * 2 + 1]);
            bI = pack2(bih0[u] + bhh0[u], 0.f);
            bF = pack2(bih0[HD + u] + bhh0[HD + u], 0.f);
            bG = pack2(bih0[2 * HD + u] + bhh0[2 * HD + u], 0.f);
            bO = pack2(bih0[3 * HD + u] + bhh0[3 * HD + u], 0.f);
        } else if (stage == 2) {  // proj: L2 biases folded here
            bI = pack2(bih1[u] + bhh1[u], 0.f);
            bF = pack2(bih1[HD + u] + bhh1[HD + u], 0.f);
            bG = pack2(bih1[2 * HD + u] + bhh1[2 * HD + u], 0.f);
            bO = pack2(bih1[3 * HD + u] + bhh1[3 * HD + u], 0.f);
        } else if (stage == 3) {  // head
            wlin_u = Wlin[u];
        }
    }
    const float blinsc = blin[0] * 0.01f;

    // ---- chunk ranges ----
    const int start_out = blockIdx.x * chl;
    if (start_out >= N) return;
    const int end_out = min(N, start_out + chl);
    const int s2      = max(0, start_out - CH_W);
    const int s1      = max(0, s2 - CH_W);
    const int span    = end_out - s1;
    const int i2      = s2 - s1;           // first L2-active step
    const int ihl     = start_out - s1;    // first head-output step

    // ---- preprocess + zero-init ----
    for (int i = tid; i < span; i += TPB) {
        float g  = grad[s1 + i];
        float lg = fminf(1.f, fmaxf(-1.f, __logf(fabsf(g) + 1e-8f) * 0.1f));
        float sg = fminf(1.f, fmaxf(-1.f, g * 22026.4657948067f));   // exp(10)
        xbuf[i] = make_float2(lg, sg);
    }
    for (int i = tid; i < RING * 32; i += TPB) {
        ((float*)h0ring)[i] = 0.f;
        ((float*)h1ring)[i] = 0.f;
        ((float4*)prring)[i] = make_float4(0.f, 0.f, 0.f, 0.f);
    }
    __syncthreads();

    float cst = 0.f, h = 0.f;
    const int NW = (span + KW - 1) / KW + 3;

    for (int w = 0; w < NW; ++w) {
        if (stage == 0) {
            const int t0 = w * KW;
            if (t0 + KW <= span) {                  // clean window
                #pragma unroll
                for (int k = 0; k < KW; ++k) { L1BODY(t0 + k); __syncwarp(); }
            } else {                                // edge window
                #pragma unroll
                for (int k = 0; k < KW; ++k) {
                    if (t0 + k < span) L1BODY(t0 + k);
                    __syncwarp();
                }
            }
        } else if (stage == 2) {
            const int t0 = (w - 1) * KW;
            if (t0 >= i2 && t0 + KW <= span) {
                #pragma unroll
                for (int k = 0; k < KW; ++k) PROJBODY(t0 + k);
            } else {
                #pragma unroll
                for (int k = 0; k < KW; ++k) {
                    const int tp = t0 + k;
                    if (tp >= i2 && tp < span) PROJBODY(tp);
                }
            }
        } else if (stage == 1) {
            const int t0 = (w - 2) * KW;
            if (t0 >= i2 && t0 + KW <= span) {
                #pragma unroll
                for (int k = 0; k < KW; ++k) { L2BODY(t0 + k); __syncwarp(); }
            } else {
                #pragma unroll
                for (int k = 0; k < KW; ++k) {
                    const int t1 = t0 + k;
                    if (t1 >= i2 && t1 < span) L2BODY(t1);
                    __syncwarp();
                }
            }
        } else {
            const int t0 = (w - 3) * KW;
            if (t0 >= ihl && t0 + KW <= span) {
                #pragma unroll
                for (int k = 0; k < KW; ++k) HEADBODY(t0 + k);
            } else {
                #pragma unroll
                for (int k = 0; k < KW; ++k) {
                    const int th = t0 + k;
                    if (th >= ihl && th < span) HEADBODY(th);
                }
            }
        }
        __syncthreads();
    }

    // final states: [update(N), h0(20), h1(20), c0(20), c1(20)]
    if (end_out == N && out_size >= N + 80 && act) {
        if (stage == 0)      { out[N + u]      = h; out[N + 40 + u] = cst; }
        else if (stage == 1) { out[N + 20 + u] = h; out[N + 60 + u] = cst; }
    }
}

extern "C" void kernel_launch(void* const* d_in, const int* in_sizes, int n_in,
                              void* d_out, int out_size) {
    const float* grad = (const float*)d_in[0];
    const float* Wih0 = (const float*)d_in[1];
    const float* Whh0 = (const float*)d_in[2];
    const float* bih0 = (const float*)d_in[3];
    const float* bhh0 = (const float*)d_in[4];
    const float* Wih1 = (const float*)d_in[5];
    const float* Whh1 = (const float*)d_in[6];
    const float* bih1 = (const float*)d_in[7];
    const float* bhh1 = (const float*)d_in[8];
    const float* Wlin = (const float*)d_in[9];
    const float* blin = (const float*)d_in[10];

    int N = in_sizes[0];
    // 592 chunk slots = 4 blocks/SM x 148 SMs, one wave
    int chl = (N + 591) / 592;
    if (chl > XB - 2 * CH_W - 1) chl = XB - 2 * CH_W - 1;
    if (chl < 1) chl = 1;
    int grid = (N + chl - 1) / chl;
    lstm_opt_kernel<<<grid, TPB>>>(grad, Wih0, Whh0, bih0, bhh0,
                                   Wih1, Whh1, bih1, bhh1, Wlin, blin,
                                   (float*)d_out, N, out_size, chl);
}

// round 15
// speedup vs baseline: 1.1792x; 1.1792x over previous
#include <cuda_runtime.h>
#include <cuda_bf16.h>
#include <math.h>

#define HD   20
#define TPB  96
#define CH_W 12
#define XB   144
#define KW   4          // steps per barrier window
#define RING 8          // 2*KW ring slots

typedef unsigned long long ull;

__device__ __forceinline__ float tanh_fast(float x) {
    float y; asm("tanh.approx.f32 %0, %1;" : "=f"(y) : "f"(x)); return y;
}
__device__ __forceinline__ ull pack2(float a, float b) {
    ull r; asm("mov.b64 %0, {%1,%2};" : "=l"(r) : "f"(a), "f"(b)); return r;
}
__device__ __forceinline__ float2 unpack2(ull p) {
    float2 v; asm("mov.b64 {%0,%1}, %2;" : "=f"(v.x), "=f"(v.y) : "l"(p)); return v;
}
__device__ __forceinline__ ull ffma2(ull a, ull b, ull c) {
    ull r; asm("fma.rn.f32x2 %0, %1, %2, %3;" : "=l"(r) : "l"(a), "l"(b), "l"(c)); return r;
}
__device__ __forceinline__ float hsum(ull p) {
    float2 v = unpack2(p); return v.x + v.y;
}

__device__ __forceinline__ void lstm_act4(ull aI, ull aF, ull aG, ull aO,
                                          float& cst, float& h) {
    float pi = hsum(aI), pf = hsum(aF), pg = hsum(aG), po = hsum(aO);
    float gi = fmaf(tanh_fast(0.5f * pi), 0.5f, 0.5f);
    float gf = fmaf(tanh_fast(0.5f * pf), 0.5f, 0.5f);
    float gg = tanh_fast(pg);
    float go = fmaf(tanh_fast(0.5f * po), 0.5f, 0.5f);
    cst = fmaf(gf, cst, gi * gg);
    h   = go * tanh_fast(cst);
}

// 20-dim dot for 4 gates; HB = float4-pair view of 20 floats (+12 zero pad).
#define DOT20(HB, aI, aF, aG, aO) do {                                        \
    _Pragma("unroll")                                                         \
    for (int j = 0; j < 5; j++) {                                             \
        ulonglong2 hp = (HB)[j];                                              \
        aI = ffma2(wI[2*j], hp.x, aI); aI = ffma2(wI[2*j+1], hp.y, aI);       \
        aF = ffma2(wF[2*j], hp.x, aF); aF = ffma2(wF[2*j+1], hp.y, aF);       \
        aG = ffma2(wG[2*j], hp.x, aG); aG = ffma2(wG[2*j+1], hp.y, aG);       \
        aO = ffma2(wO[2*j], hp.x, aO); aO = ffma2(wO[2*j+1], hp.y, aO);       \
    }                                                                         \
} while (0)

// Stage bodies (T = absolute step index within [0, span))
#define L1BODY(T) do {                                                        \
    float2 xv = xbuf[T];                                                      \
    ull xp = pack2(xv.x, xv.y);                                               \
    ull aI = ffma2(wxI, xp, bI);                                              \
    ull aF = ffma2(wxF, xp, bF);                                              \
    ull aG = ffma2(wxG, xp, bG);                                              \
    ull aO = ffma2(wxO, xp, bO);                                              \
    const ulonglong2* hb =                                                    \
        (const ulonglong2*)h0ring[((T) + RING - 1) & (RING - 1)];             \
    DOT20(hb, aI, aF, aG, aO);                                                \
    lstm_act4(aI, aF, aG, aO, cst, h);                                        \
    h0ring[(T) & (RING - 1)][u] = h;                                          \
} while (0)

#define PROJBODY(T) do {                                                      \
    ull aI = bI, aF = bF, aG = bG, aO = bO;                                   \
    const ulonglong2* yb = (const ulonglong2*)h0ring[(T) & (RING - 1)];       \
    DOT20(yb, aI, aF, aG, aO);                                                \
    prring[(T) & (RING - 1)][u] =                                             \
        make_float4(hsum(aI), hsum(aF), hsum(aG), hsum(aO));                  \
} while (0)

#define L2BODY(T) do {                                                        \
    float4 pv = prring[(T) & (RING - 1)][u];                                  \
    ull aI = pack2(pv.x, 0.f), aF = pack2(pv.y, 0.f);                         \
    ull aG = pack2(pv.z, 0.f), aO = pack2(pv.w, 0.f);                         \
    const ulonglong2* hb =                                                    \
        (const ulonglong2*)h1ring[((T) + RING - 1) & (RING - 1)];             \
    DOT20(hb, aI, aF, aG, aO);                                                \
    lstm_act4(aI, aF, aG, aO, cst, h);                                        \
    h1ring[(T) & (RING - 1)][u] = h;                                          \
} while (0)

#define HEADBODY(T) do {                                                      \
    float hv = h1ring[(T) & (RING - 1)][u];                                   \
    float part = hv * wlin_u;                                                 \
    part += __shfl_xor_sync(0xFFFFFFFFu, part, 16);                           \
    part += __shfl_xor_sync(0xFFFFFFFFu, part, 8);                            \
    part += __shfl_xor_sync(0xFFFFFFFFu, part, 4);                            \
    part += __shfl_xor_sync(0xFFFFFFFFu, part, 2);                            \
    part += __shfl_xor_sync(0xFFFFFFFFu, part, 1);                            \
    if (lane == 0) out[s1 + (T)] = fmaf(part, 0.01f, blinsc);                 \
} while (0)

// 96 threads/block, ONE chunk per block, 3-warp window pipeline (KW=4),
// 5 blocks/SM (480 thr x 128 regs = 61440 regs <= 64K):
//   w0: L1 LSTM  window w    -> h0ring[t&7]
//   w1: L2 LSTM  window w-2  -> h1ring[t1&7]
//   w2: proj     window w-1  -> prring[tp&7]; then linear head @ window w-3
// NO stage rotation: same-stage warps share an SMSP -> perfect L0 I$ reuse
// (R14 showed rotation thrashes I$ for a 26% regression).
__global__ __launch_bounds__(TPB, 5)
void lstm_opt_kernel(const float* __restrict__ grad,
                     const float* __restrict__ Wih0, const float* __restrict__ Whh0,
                     const float* __restrict__ bih0, const float* __restrict__ bhh0,
                     const float* __restrict__ Wih1, const float* __restrict__ Whh1,
                     const float* __restrict__ bih1, const float* __restrict__ bhh1,
                     const float* __restrict__ Wlin, const float* __restrict__ blin,
                     float* __restrict__ out, int N, int out_size, int chl)
{
    __shared__ __align__(16) float2 xbuf[XB];
    __shared__ __align__(16) float  h0ring[RING][32];
    __shared__ __align__(16) float4 prring[RING][32];
    __shared__ __align__(16) float  h1ring[RING][32];

    const int tid  = threadIdx.x;
    const int wid  = tid >> 5;
    const int lane = tid & 31;
    const int u    = lane;
    const bool act = (u < HD);

    // ---- per-warp weights: per-gate, k-pair packed ----
    ull wI[10], wF[10], wG[10], wO[10];
    ull bI = 0ull, bF = 0ull, bG = 0ull, bO = 0ull;
    ull wxI = 0ull, wxF = 0ull, wxG = 0ull, wxO = 0ull;
    float wlin_u = 0.f;
    #pragma unroll
    for (int k = 0; k < 10; k++) { wI[k]=0ull; wF[k]=0ull; wG[k]=0ull; wO[k]=0ull; }

    if (act) {
        const float* W = (wid == 0) ? Whh0 : (wid == 1) ? Whh1 : Wih1;
        #pragma unroll
        for (int k = 0; k < 10; k++) {
            wI[k] = pack2(W[u * HD + 2*k],            W[u * HD + 2*k + 1]);
            wF[k] = pack2(W[(HD + u) * HD + 2*k],     W[(HD + u) * HD + 2*k + 1]);
            wG[k] = pack2(W[(2 * HD + u) * HD + 2*k], W[(2 * HD + u) * HD + 2*k + 1]);
            wO[k] = pack2(W[(3 * HD + u) * HD + 2*k], W[(3 * HD + u) * HD + 2*k + 1]);
        }
        if (wid == 0) {           // L1: x-projection weights + L1 biases
            wxI = pack2(Wih0[u * 2 + 0],            Wih0[u * 2 + 1]);
            wxF = pack2(Wih0[(HD + u) * 2 + 0],     Wih0[(HD + u) * 2 + 1]);
            wxG = pack2(Wih0[(2 * HD + u) * 2 + 0], Wih0[(2 * HD + u) * 2 + 1]);
            wxO = pack2(Wih0[(3 * HD + u) * 2 + 0], Wih0[(3 * HD + u) * 2 + 1]);
            bI = pack2(bih0[u] + bhh0[u], 0.f);
            bF = pack2(bih0[HD + u] + bhh0[HD + u], 0.f);
            bG = pack2(bih0[2 * HD + u] + bhh0[2 * HD + u], 0.f);
            bO = pack2(bih0[3 * HD + u] + bhh0[3 * HD + u], 0.f);
        } else if (wid == 2) {    // proj: L2 biases folded here; head weights
            bI = pack2(bih1[u] + bhh1[u], 0.f);
            bF = pack2(bih1[HD + u] + bhh1[HD + u], 0.f);
            bG = pack2(bih1[2 * HD + u] + bhh1[2 * HD + u], 0.f);
            bO = pack2(bih1[3 * HD + u] + bhh1[3 * HD + u], 0.f);
            wlin_u = Wlin[u];
        }
    }
    const float blinsc = blin[0] * 0.01f;

    // ---- chunk ranges ----
    const int start_out = blockIdx.x * chl;
    if (start_out >= N) return;
    const int end_out = min(N, start_out + chl);
    const int s2      = max(0, start_out - CH_W);
    const int s1      = max(0, s2 - CH_W);
    const int span    = end_out - s1;
    const int i2      = s2 - s1;           // first L2-active step
    const int ihl     = start_out - s1;    // first head-output step

    // ---- preprocess + zero-init ----
    for (int i = tid; i < span; i += TPB) {
        float g  = grad[s1 + i];
        float lg = fminf(1.f, fmaxf(-1.f, __logf(fabsf(g) + 1e-8f) * 0.1f));
        float sg = fminf(1.f, fmaxf(-1.f, g * 22026.4657948067f));   // exp(10)
        xbuf[i] = make_float2(lg, sg);
    }
    for (int i = tid; i < RING * 32; i += TPB) {
        ((float*)h0ring)[i] = 0.f;
        ((float*)h1ring)[i] = 0.f;
        ((float4*)prring)[i] = make_float4(0.f, 0.f, 0.f, 0.f);
    }
    __syncthreads();

    float cst = 0.f, h = 0.f;
    const int NW = (span + KW - 1) / KW + 3;

    for (int w = 0; w < NW; ++w) {
        if (wid == 0) {
            const int t0 = w * KW;
            if (t0 + KW <= span) {                  // clean window
                #pragma unroll
                for (int k = 0; k < KW; ++k) { L1BODY(t0 + k); __syncwarp(); }
            } else {                                // edge window
                #pragma unroll
                for (int k = 0; k < KW; ++k) {
                    if (t0 + k < span) L1BODY(t0 + k);
                    __syncwarp();
                }
            }
        } else if (wid == 1) {
            const int t0 = (w - 2) * KW;
            if (t0 >= i2 && t0 + KW <= span) {
                #pragma unroll
                for (int k = 0; k < KW; ++k) { L2BODY(t0 + k); __syncwarp(); }
            } else {
                #pragma unroll
                for (int k = 0; k < KW; ++k) {
                    const int t1 = t0 + k;
                    if (t1 >= i2 && t1 < span) L2BODY(t1);
                    __syncwarp();
                }
            }
        } else {
            // ---- proj @ window w-1 ----
            const int t0 = (w - 1) * KW;
            if (t0 >= i2 && t0 + KW <= span) {
                #pragma unroll
                for (int k = 0; k < KW; ++k) PROJBODY(t0 + k);
            } else {
                #pragma unroll
                for (int k = 0; k < KW; ++k) {
                    const int tp = t0 + k;
                    if (tp >= i2 && tp < span) PROJBODY(tp);
                }
            }
            // ---- head @ window w-3 (h1ring written @ w-2 last window) ----
            const int th0 = (w - 3) * KW;
            if (th0 >= ihl && th0 + KW <= span) {
                #pragma unroll
                for (int k = 0; k < KW; ++k) HEADBODY(th0 + k);
            } else {
                #pragma unroll
                for (int k = 0; k < KW; ++k) {
                    const int th = th0 + k;
                    if (th >= ihl && th < span) HEADBODY(th);
                }
            }
        }
        __syncthreads();
    }

    // final states: [update(N), h0(20), h1(20), c0(20), c1(20)]
    if (end_out == N && out_size >= N + 80 && act) {
        if (wid == 0)      { out[N + u]      = h; out[N + 40 + u] = cst; }
        else if (wid == 1) { out[N + 20 + u] = h; out[N + 60 + u] = cst; }
    }
}

extern "C" void kernel_launch(void* const* d_in, const int* in_sizes, int n_in,
                              void* d_out, int out_size) {
    const float* grad = (const float*)d_in[0];
    const float* Wih0 = (const float*)d_in[1];
    const float* Whh0 = (const float*)d_in[2];
    const float* bih0 = (const float*)d_in[3];
    const float* bhh0 = (const float*)d_in[4];
    const float* Wih1 = (const float*)d_in[5];
    const float* Whh1 = (const float*)d_in[6];
    const float* bih1 = (const float*)d_in[7];
    const float* bhh1 = (const float*)d_in[8];
    const float* Wlin = (const float*)d_in[9];
    const float* blin = (const float*)d_in[10];

    int N = in_sizes[0];
    // 740 chunk slots = 5 blocks/SM x 148 SMs, one wave
    int chl = (N + 739) / 740;
    if (chl > XB - 2 * CH_W - 1) chl = XB - 2 * CH_W - 1;
    if (chl < 1) chl = 1;
    int grid = (N + chl - 1) / chl;
    lstm_opt_kernel<<<grid, TPB>>>(grad, Wih0, Whh0, bih0, bhh0,
                                   Wih1, Whh1, bih1, bhh1, Wlin, blin,
                                   (float*)d_out, N, out_size, chl);
}

// round 16
// speedup vs baseline: 1.3191x; 1.1187x over previous
#include <cuda_runtime.h>
#include <cuda_bf16.h>
#include <math.h>

#define HD   20
#define TPB  128
#define CH_W 12
#define XB   144
#define KW   4          // steps per barrier window
#define RING 8          // 2*KW ring slots

typedef unsigned long long ull;

__device__ __forceinline__ float tanh_fast(float x) {
    float y; asm("tanh.approx.f32 %0, %1;" : "=f"(y) : "f"(x)); return y;
}
__device__ __forceinline__ ull pack2(float a, float b) {
    ull r; asm("mov.b64 %0, {%1,%2};" : "=l"(r) : "f"(a), "f"(b)); return r;
}
__device__ __forceinline__ float2 unpack2(ull p) {
    float2 v; asm("mov.b64 {%0,%1}, %2;" : "=f"(v.x), "=f"(v.y) : "l"(p)); return v;
}
__device__ __forceinline__ ull ffma2(ull a, ull b, ull c) {
    ull r; asm("fma.rn.f32x2 %0, %1, %2, %3;" : "=l"(r) : "l"(a), "l"(b), "l"(c)); return r;
}
__device__ __forceinline__ float hsum(ull p) {
    float2 v = unpack2(p); return v.x + v.y;
}

// one k-packed 20-dim row dot (10 ffma2) against h regs hA..hE
#define ROW10(W, A) do {                                                      \
    A = ffma2((W)[0], hA.x, A); A = ffma2((W)[1], hA.y, A);                   \
    A = ffma2((W)[2], hB.x, A); A = ffma2((W)[3], hB.y, A);                   \
    A = ffma2((W)[4], hC.x, A); A = ffma2((W)[5], hC.y, A);                   \
    A = ffma2((W)[6], hD.x, A); A = ffma2((W)[7], hD.y, A);                   \
    A = ffma2((W)[8], hE.x, A); A = ffma2((W)[9], hE.y, A);                   \
} while (0)

// gate activations + cell update from 4 scalar pre-acts (lane u < 20)
#define ACT4(PI, PF, PG, PO, CST, H) do {                                     \
    float gi = fmaf(tanh_fast(0.5f * (PI)), 0.5f, 0.5f);                      \
    float gf = fmaf(tanh_fast(0.5f * (PF)), 0.5f, 0.5f);                      \
    float gg = tanh_fast(PG);                                                 \
    float go = fmaf(tanh_fast(0.5f * (PO)), 0.5f, 0.5f);                      \
    CST = fmaf(gf, CST, gi * gg);                                             \
    H   = go * tanh_fast(CST);                                                \
} while (0)

// ---- stage bodies; rows spread over ALL 32 lanes: lane l owns rows
//      r0=l, r1=l+32, r2=(l+64)%80 (wrap rows duplicate identical work) ----
#define L1BODY(T) do {                                                        \
    float2 xv = xbuf[T];                                                      \
    ull xp = pack2(xv.x, xv.y);                                               \
    const ulonglong2* hb =                                                    \
        (const ulonglong2*)h0ring[((T) + RING - 1) & (RING - 1)];             \
    ulonglong2 hA = hb[0], hB = hb[1], hC = hb[2], hD = hb[3], hE = hb[4];    \
    ull a0 = ffma2(wx0, xp, bia0);                                            \
    ull a1 = ffma2(wx1, xp, bia1);                                            \
    ull a2 = ffma2(wx2, xp, bia2);                                            \
    ROW10(w0, a0); ROW10(w1, a1); ROW10(w2, a2);                              \
    scr[r0] = hsum(a0); scr[r1] = hsum(a1); scr[r2] = hsum(a2);               \
    __syncwarp();                                                             \
    if (act) {                                                                \
        float pi = scr[u], pf = scr[20 + u], pg = scr[40 + u], po = scr[60 + u]; \
        ACT4(pi, pf, pg, po, cst, h);                                         \
        h0ring[(T) & (RING - 1)][u] = h;                                      \
    }                                                                         \
    __syncwarp();                                                             \
} while (0)

#define PROJBODY(T) do {                                                      \
    const ulonglong2* hb = (const ulonglong2*)h0ring[(T) & (RING - 1)];       \
    ulonglong2 hA = hb[0], hB = hb[1], hC = hb[2], hD = hb[3], hE = hb[4];    \
    ull a0 = bia0, a1 = bia1, a2 = bia2;                                      \
    ROW10(w0, a0); ROW10(w1, a1); ROW10(w2, a2);                              \
    float* pd = prring[(T) & (RING - 1)];                                     \
    pd[r0] = hsum(a0); pd[r1] = hsum(a1); pd[r2] = hsum(a2);                  \
} while (0)

#define L2BODY(T) do {                                                        \
    const ulonglong2* hb =                                                    \
        (const ulonglong2*)h1ring[((T) + RING - 1) & (RING - 1)];             \
    ulonglong2 hA = hb[0], hB = hb[1], hC = hb[2], hD = hb[3], hE = hb[4];    \
    const float* pv = prring[(T) & (RING - 1)];                               \
    ull a0 = pack2(pv[r0], 0.f);                                              \
    ull a1 = pack2(pv[r1], 0.f);                                              \
    ull a2 = pack2(pv[r2], 0.f);                                              \
    ROW10(w0, a0); ROW10(w1, a1); ROW10(w2, a2);                              \
    scr[r0] = hsum(a0); scr[r1] = hsum(a1); scr[r2] = hsum(a2);               \
    __syncwarp();                                                             \
    if (act) {                                                                \
        float pi = scr[u], pf = scr[20 + u], pg = scr[40 + u], po = scr[60 + u]; \
        ACT4(pi, pf, pg, po, cst, h);                                         \
        h1ring[(T) & (RING - 1)][u] = h;                                      \
    }                                                                         \
    __syncwarp();                                                             \
} while (0)

#define HEADBODY(T) do {                                                      \
    float hv = h1ring[(T) & (RING - 1)][u];                                   \
    float part = hv * wlin_u;                                                 \
    part += __shfl_xor_sync(0xFFFFFFFFu, part, 16);                           \
    part += __shfl_xor_sync(0xFFFFFFFFu, part, 8);                            \
    part += __shfl_xor_sync(0xFFFFFFFFu, part, 4);                            \
    part += __shfl_xor_sync(0xFFFFFFFFu, part, 2);                            \
    part += __shfl_xor_sync(0xFFFFFFFFu, part, 1);                            \
    if (lane == 0) out[s1 + (T)] = fmaf(part, 0.01f, blinsc);                 \
} while (0)

// 128 threads/block, ONE chunk per block, 4-warp window pipeline (KW=4),
// 4 blocks/SM. NO stage rotation (R14: rotation thrashes L0 I$, -26%).
//   w0 (SMSP0): L1 LSTM  window w    -> h0ring[t&7]
//   w2 (SMSP2): proj     window w-1  -> prring[tp&7] (flat [80] rows)
//   w1 (SMSP1): L2 LSTM  window w-2  -> h1ring[t1&7]
//   w3 (SMSP3): linear head + store, window w-3
// Row spreading: the 80 gate-rows of each 4H x H GEMV are distributed over
// all 32 lanes (3 rows each, wrap-duplicated), cutting the pacing warp's
// FFMA2 count 40 -> 30 and LDS.128 6 -> 5 per step. The per-unit cell
// update gathers pre-acts from a [80]-float scratch after a __syncwarp.
__global__ __launch_bounds__(TPB, 4)
void lstm_opt_kernel(const float* __restrict__ grad,
                     const float* __restrict__ Wih0, const float* __restrict__ Whh0,
                     const float* __restrict__ bih0, const float* __restrict__ bhh0,
                     const float* __restrict__ Wih1, const float* __restrict__ Whh1,
                     const float* __restrict__ bih1, const float* __restrict__ bhh1,
                     const float* __restrict__ Wlin, const float* __restrict__ blin,
                     float* __restrict__ out, int N, int out_size, int chl)
{
    __shared__ __align__(16) float2 xbuf[XB];
    __shared__ __align__(16) float h0ring[RING][32];
    __shared__ __align__(16) float h1ring[RING][32];
    __shared__ __align__(16) float prring[RING][80];
    __shared__ __align__(16) float scr1[80];
    __shared__ __align__(16) float scr2[80];

    const int tid  = threadIdx.x;
    const int wid  = tid >> 5;
    const int lane = tid & 31;
    const int u    = lane;
    const bool act = (u < HD);
    const int r0 = lane, r1 = lane + 32, r2 = (lane + 64) % 80;
    float* const scr = (wid == 0) ? scr1 : scr2;   // per-stage scratch

    // ---- per-warp weights: 3 k-packed rows per lane ----
    ull w0[10], w1[10], w2[10];
    ull bia0 = 0ull, bia1 = 0ull, bia2 = 0ull;
    ull wx0 = 0ull, wx1 = 0ull, wx2 = 0ull;
    float wlin_u = 0.f;
    #pragma unroll
    for (int k = 0; k < 10; k++) { w0[k] = 0ull; w1[k] = 0ull; w2[k] = 0ull; }

    if (wid < 3) {
        const float* W = (wid == 0) ? Whh0 : (wid == 1) ? Whh1 : Wih1;
        #pragma unroll
        for (int k = 0; k < 10; k++) {
            w0[k] = pack2(W[r0 * HD + 2*k], W[r0 * HD + 2*k + 1]);
            w1[k] = pack2(W[r1 * HD + 2*k], W[r1 * HD + 2*k + 1]);
            w2[k] = pack2(W[r2 * HD + 2*k], W[r2 * HD + 2*k + 1]);
        }
        if (wid == 0) {           // L1: x-weights + L1 biases per row
            wx0 = pack2(Wih0[r0 * 2], Wih0[r0 * 2 + 1]);
            wx1 = pack2(Wih0[r1 * 2], Wih0[r1 * 2 + 1]);
            wx2 = pack2(Wih0[r2 * 2], Wih0[r2 * 2 + 1]);
            bia0 = pack2(bih0[r0] + bhh0[r0], 0.f);
            bia1 = pack2(bih0[r1] + bhh0[r1], 0.f);
            bia2 = pack2(bih0[r2] + bhh0[r2], 0.f);
        } else if (wid == 2) {    // proj: L2 biases folded here
            bia0 = pack2(bih1[r0] + bhh1[r0], 0.f);
            bia1 = pack2(bih1[r1] + bhh1[r1], 0.f);
            bia2 = pack2(bih1[r2] + bhh1[r2], 0.f);
        }
    } else if (act) {             // head
        wlin_u = Wlin[u];
    }
    const float blinsc = blin[0] * 0.01f;

    // ---- chunk ranges ----
    const int start_out = blockIdx.x * chl;
    if (start_out >= N) return;
    const int end_out = min(N, start_out + chl);
    const int s2      = max(0, start_out - CH_W);
    const int s1      = max(0, s2 - CH_W);
    const int span    = end_out - s1;
    const int i2      = s2 - s1;           // first L2-active step
    const int ihl     = start_out - s1;    // first head-output step

    // ---- preprocess + zero-init ----
    for (int i = tid; i < span; i += TPB) {
        float g  = grad[s1 + i];
        float lg = fminf(1.f, fmaxf(-1.f, __logf(fabsf(g) + 1e-8f) * 0.1f));
        float sg = fminf(1.f, fmaxf(-1.f, g * 22026.4657948067f));   // exp(10)
        xbuf[i] = make_float2(lg, sg);
    }
    for (int i = tid; i < RING * 32; i += TPB) {
        ((float*)h0ring)[i] = 0.f;
        ((float*)h1ring)[i] = 0.f;
    }
    for (int i = tid; i < RING * 80; i += TPB) ((float*)prring)[i] = 0.f;
    __syncthreads();

    float cst = 0.f, h = 0.f;
    const int NW = (span + KW - 1) / KW + 3;

    for (int w = 0; w < NW; ++w) {
        if (wid == 0) {
            const int t0 = w * KW;
            if (t0 + KW <= span) {                  // clean window
                #pragma unroll
                for (int k = 0; k < KW; ++k) L1BODY(t0 + k);
            } else {                                // edge window
                #pragma unroll
                for (int k = 0; k < KW; ++k) {
                    if (t0 + k < span) L1BODY(t0 + k);
                }
            }
        } else if (wid == 2) {
            const int t0 = (w - 1) * KW;
            if (t0 >= i2 && t0 + KW <= span) {
                #pragma unroll
                for (int k = 0; k < KW; ++k) PROJBODY(t0 + k);
            } else {
                #pragma unroll
                for (int k = 0; k < KW; ++k) {
                    const int tp = t0 + k;
                    if (tp >= i2 && tp < span) PROJBODY(tp);
                }
            }
        } else if (wid == 1) {
            const int t0 = (w - 2) * KW;
            if (t0 >= i2 && t0 + KW <= span) {
                #pragma unroll
                for (int k = 0; k < KW; ++k) L2BODY(t0 + k);
            } else {
                #pragma unroll
                for (int k = 0; k < KW; ++k) {
                    const int t1 = t0 + k;
                    if (t1 >= i2 && t1 < span) L2BODY(t1);
                }
            }
        } else {
            const int t0 = (w - 3) * KW;
            if (t0 >= ihl && t0 + KW <= span) {
                #pragma unroll
                for (int k = 0; k < KW; ++k) HEADBODY(t0 + k);
            } else {
                #pragma unroll
                for (int k = 0; k < KW; ++k) {
                    const int th = t0 + k;
                    if (th >= ihl && th < span) HEADBODY(th);
                }
            }
        }
        __syncthreads();
    }

    // final states: [update(N), h0(20), h1(20), c0(20), c1(20)]
    if (end_out == N && out_size >= N + 80 && act) {
        if (wid == 0)      { out[N + u]      = h; out[N + 40 + u] = cst; }
        else if (wid == 1) { out[N + 20 + u] = h; out[N + 60 + u] = cst; }
    }
}

extern "C" void kernel_launch(void* const* d_in, const int* in_sizes, int n_in,
                              void* d_out, int out_size) {
    const float* grad = (const float*)d_in[0];
    const float* Wih0 = (const float*)d_in[1];
    const float* Whh0 = (const float*)d_in[2];
    const float* bih0 = (const float*)d_in[3];
    const float* bhh0 = (const float*)d_in[4];
    const float* Wih1 = (const float*)d_in[5];
    const float* Whh1 = (const float*)d_in[6];
    const float* bih1 = (const float*)d_in[7];
    const float* bhh1 = (const float*)d_in[8];
    const float* Wlin = (const float*)d_in[9];
    const float* blin = (const float*)d_in[10];

    int N = in_sizes[0];
    // 592 chunk slots = 4 blocks/SM x 148 SMs, one wave
    int chl = (N + 591) / 592;
    if (chl > XB - 2 * CH_W - 1) chl = XB - 2 * CH_W - 1;
    if (chl < 1) chl = 1;
    int grid = (N + chl - 1) / chl;
    lstm_opt_kernel<<<grid, TPB>>>(grad, Wih0, Whh0, bih0, bhh0,
                                   Wih1, Whh1, bih1, bhh1, Wlin, blin,
                                   (float*)d_out, N, out_size, chl);
}